// round 3
// baseline (speedup 1.0000x reference)
#include <cuda_runtime.h>
#include <cstdint>
#include <math.h>

#define S_LEN   2048
#define BATCH   2
#define DMODEL  1024
#define NHEADS  16
#define DHEAD   64
#define MROWS   (BATCH * S_LEN)   // 4096
#define IGNORE_VAL (-100000.0f)

// ---------------- scratch (no allocations allowed) ----------------
__device__ float g_q[MROWS * DMODEL];
__device__ float g_k[MROWS * DMODEL];
__device__ float g_v[MROWS * DMODEL];
__device__ float g_z[MROWS * DMODEL];

// ---------------- helpers ----------------
__device__ __forceinline__ uint32_t f2tf32(float f) {
    uint32_t r;
    asm("cvt.rna.tf32.f32 %0, %1;" : "=r"(r) : "f"(f));
    return r;
}

__device__ __forceinline__ void mma_tf32_16x8x8(
    float* d, const uint32_t* a, const uint32_t* b, const float* c)
{
    asm volatile(
        "mma.sync.aligned.m16n8k8.row.col.f32.tf32.tf32.f32 "
        "{%0,%1,%2,%3}, {%4,%5,%6,%7}, {%8,%9}, {%10,%11,%12,%13};\n"
        : "=f"(d[0]), "=f"(d[1]), "=f"(d[2]), "=f"(d[3])
        : "r"(a[0]), "r"(a[1]), "r"(a[2]), "r"(a[3]),
          "r"(b[0]), "r"(b[1]),
          "f"(c[0]), "f"(c[1]), "f"(c[2]), "f"(c[3]));
}

// ============ tf32 mma.sync GEMM: C[M,N] = A[M,K] * Bop[N,K]^T + bias[N] ============
// mode 0: W is [H=16, K=1024, D=64];  Bop[n][k] = W[n>>6][k][n&63]
// mode 1: W is [K=1024, N=1024] row-major;  Bop[n][k] = W[k*DMODEL + n]
// grid (N/128, M/128), 256 threads (8 warps: 2 along M x 4 along N; warp tile 64x32).
#define KC   32            // k-chunk
#define TS   36            // smem row stride (words)

__global__ __launch_bounds__(256) void tf32_gemm(
    const float* __restrict__ A, const float* __restrict__ W,
    const float* __restrict__ bias, float* __restrict__ C, int mode)
{
    __shared__ uint32_t As[128 * TS];
    __shared__ uint32_t Bs[128 * TS];

    const int tid = threadIdx.x;
    const int wid = tid >> 5;
    const int lid = tid & 31;
    const int g   = lid >> 2;        // groupID 0..7
    const int tig = lid & 3;         // thread-in-group 0..3

    const int wm = wid >> 2;         // 0..1  (M)
    const int wn = wid & 3;          // 0..3  (N)

    const int n0 = blockIdx.x * 128;
    const int m0 = blockIdx.y * 128;

    float acc[4][4][4];              // [mi][nj][frag]
#pragma unroll
    for (int i = 0; i < 4; i++)
#pragma unroll
        for (int j = 0; j < 4; j++)
#pragma unroll
            for (int f = 0; f < 4; f++) acc[i][j][f] = 0.0f;

    // B gather indexing
    const int ng = n0 + (tid & 127);         // this thread's n row
    const int khalf = (tid >> 7) * 16;       // 0 or 16: k sub-range

    for (int k0 = 0; k0 < DMODEL; k0 += KC) {
        __syncthreads();
        // ---- A tile: 128 rows x 32 k, float4 loads, cvt to tf32 ----
#pragma unroll
        for (int it = 0; it < 4; it++) {
            int i = tid + it * 256;          // 0..1023
            int row = i >> 3;
            int j = i & 7;
            float4 v = *(const float4*)(A + (size_t)(m0 + row) * DMODEL + k0 + j * 4);
            uint32_t* dst = As + row * TS + j * 4;
            dst[0] = f2tf32(v.x);
            dst[1] = f2tf32(v.y);
            dst[2] = f2tf32(v.z);
            dst[3] = f2tf32(v.w);
        }
        // ---- B tile: 128 n-rows x 32 k ----
        if (mode == 0) {
            const float* wb = W + (size_t)(ng >> 6) * (DMODEL * DHEAD) + (ng & 63);
#pragma unroll
            for (int k = 0; k < 16; k++) {
                float v = wb[(size_t)(k0 + khalf + k) * DHEAD];
                Bs[(tid & 127) * TS + khalf + k] = f2tf32(v);
            }
        } else {
            const float* wb = W + ng;
#pragma unroll
            for (int k = 0; k < 16; k++) {
                float v = wb[(size_t)(k0 + khalf + k) * DMODEL];
                Bs[(tid & 127) * TS + khalf + k] = f2tf32(v);
            }
        }
        __syncthreads();

        // ---- compute: 4 k-steps of 8 ----
#pragma unroll
        for (int kk = 0; kk < KC; kk += 8) {
            uint32_t af[4][4];       // [mi][frag]
            uint32_t bf[4][2];       // [nj][frag]
#pragma unroll
            for (int mi = 0; mi < 4; mi++) {
                int r = wm * 64 + mi * 16 + g;
                af[mi][0] = As[r * TS + kk + tig];
                af[mi][1] = As[(r + 8) * TS + kk + tig];
                af[mi][2] = As[r * TS + kk + tig + 4];
                af[mi][3] = As[(r + 8) * TS + kk + tig + 4];
            }
#pragma unroll
            for (int nj = 0; nj < 4; nj++) {
                int n = wn * 32 + nj * 8 + g;
                bf[nj][0] = Bs[n * TS + kk + tig];
                bf[nj][1] = Bs[n * TS + kk + tig + 4];
            }
#pragma unroll
            for (int mi = 0; mi < 4; mi++)
#pragma unroll
                for (int nj = 0; nj < 4; nj++)
                    mma_tf32_16x8x8(acc[mi][nj], af[mi], bf[nj], acc[mi][nj]);
        }
    }

    // ---- epilogue: write with bias ----
#pragma unroll
    for (int mi = 0; mi < 4; mi++) {
        int r0 = m0 + wm * 64 + mi * 16 + g;
#pragma unroll
        for (int nj = 0; nj < 4; nj++) {
            int c0 = n0 + wn * 32 + nj * 8 + tig * 2;
            float b0 = bias[c0], b1 = bias[c0 + 1];
            float2 v0 = make_float2(acc[mi][nj][0] + b0, acc[mi][nj][1] + b1);
            float2 v1 = make_float2(acc[mi][nj][2] + b0, acc[mi][nj][3] + b1);
            *(float2*)(C + (size_t)r0 * DMODEL + c0) = v0;
            *(float2*)(C + (size_t)(r0 + 8) * DMODEL + c0) = v1;
        }
    }
}

// ---------------- flash attention (causal + additive mask) ----------------
#define FL_LDS 68

__global__ __launch_bounds__(256) void flash_attn(
    const float* __restrict__ q, const float* __restrict__ k,
    const float* __restrict__ v, const float* __restrict__ amask,
    float* __restrict__ z)
{
    extern __shared__ float sm[];
    float* Qs = sm;
    float* Ks = sm + 64 * FL_LDS;
    float* Vs = sm + 2 * 64 * FL_LDS;
    float* Ps = sm + 3 * 64 * FL_LDS;

    const int qt = blockIdx.x;
    const int h  = blockIdx.y;
    const int b  = blockIdx.z;
    const int tid = threadIdx.x;
    const int tx = tid & 15;
    const int ty = tid >> 4;
    const int i0 = ty * 4;
    const int j0 = tx * 4;
    const int d0 = tx * 4;

    const size_t baseRow = (size_t)b * S_LEN;
    const int lr = tid >> 4;
    const int lc = tid & 15;

#pragma unroll
    for (int rr = 0; rr < 64; rr += 16) {
        int row = lr + rr;
        *(float4*)(Qs + row * FL_LDS + lc * 4) =
            *(const float4*)(q + (baseRow + qt * 64 + row) * DMODEL + h * 64 + lc * 4);
    }

    float m_prev[4], l_sum[4], o[4][4];
#pragma unroll
    for (int r = 0; r < 4; r++) {
        m_prev[r] = -1e30f;
        l_sum[r] = 0.0f;
#pragma unroll
        for (int c = 0; c < 4; c++) o[r][c] = 0.0f;
    }

    for (int kt = 0; kt <= qt; kt++) {
        __syncthreads();
#pragma unroll
        for (int rr = 0; rr < 64; rr += 16) {
            int row = lr + rr;
            *(float4*)(Ks + row * FL_LDS + lc * 4) =
                *(const float4*)(k + (baseRow + kt * 64 + row) * DMODEL + h * 64 + lc * 4);
            *(float4*)(Vs + row * FL_LDS + lc * 4) =
                *(const float4*)(v + (baseRow + kt * 64 + row) * DMODEL + h * 64 + lc * 4);
        }
        __syncthreads();

        float sacc[4][4];
#pragma unroll
        for (int r = 0; r < 4; r++)
#pragma unroll
            for (int c = 0; c < 4; c++) sacc[r][c] = 0.0f;

        for (int d = 0; d < 64; d += 4) {
            float4 qr[4], kr[4];
#pragma unroll
            for (int r = 0; r < 4; r++) qr[r] = *(float4*)(Qs + (i0 + r) * FL_LDS + d);
#pragma unroll
            for (int c = 0; c < 4; c++) kr[c] = *(float4*)(Ks + (j0 + c) * FL_LDS + d);
#pragma unroll
            for (int r = 0; r < 4; r++)
#pragma unroll
                for (int c = 0; c < 4; c++)
                    sacc[r][c] += qr[r].x * kr[c].x + qr[r].y * kr[c].y +
                                  qr[r].z * kr[c].z + qr[r].w * kr[c].w;
        }

#pragma unroll
        for (int r = 0; r < 4; r++) {
            int qi = qt * 64 + i0 + r;
#pragma unroll
            for (int c = 0; c < 4; c++) {
                int kj = kt * 64 + j0 + c;
                float s = (kj <= qi) ? sacc[r][c] * 0.125f : IGNORE_VAL;
                s += amask[b * S_LEN + kj];
                sacc[r][c] = s;
            }
        }

        float tm[4];
#pragma unroll
        for (int r = 0; r < 4; r++) {
            float mx = fmaxf(fmaxf(sacc[r][0], sacc[r][1]), fmaxf(sacc[r][2], sacc[r][3]));
#pragma unroll
            for (int msk = 1; msk < 16; msk <<= 1)
                mx = fmaxf(mx, __shfl_xor_sync(0xffffffffu, mx, msk));
            tm[r] = mx;
        }

#pragma unroll
        for (int r = 0; r < 4; r++) {
            float mn = fmaxf(m_prev[r], tm[r]);
            float alpha = __expf(m_prev[r] - mn);
            float rsum = 0.0f;
#pragma unroll
            for (int c = 0; c < 4; c++) {
                float p = __expf(sacc[r][c] - mn);
                sacc[r][c] = p;
                rsum += p;
            }
#pragma unroll
            for (int msk = 1; msk < 16; msk <<= 1)
                rsum += __shfl_xor_sync(0xffffffffu, rsum, msk);
            l_sum[r] = l_sum[r] * alpha + rsum;
            m_prev[r] = mn;
#pragma unroll
            for (int c = 0; c < 4; c++) o[r][c] *= alpha;
        }

#pragma unroll
        for (int r = 0; r < 4; r++)
#pragma unroll
            for (int c = 0; c < 4; c++)
                Ps[(i0 + r) * FL_LDS + j0 + c] = sacc[r][c];
        __syncthreads();

        for (int j = 0; j < 64; j++) {
            float4 vv = *(float4*)(Vs + j * FL_LDS + d0);
#pragma unroll
            for (int r = 0; r < 4; r++) {
                float p = Ps[(i0 + r) * FL_LDS + j];
                o[r][0] += p * vv.x;
                o[r][1] += p * vv.y;
                o[r][2] += p * vv.z;
                o[r][3] += p * vv.w;
            }
        }
    }

#pragma unroll
    for (int r = 0; r < 4; r++) {
        float inv = 1.0f / l_sum[r];
        int row = qt * 64 + i0 + r;
        float4 outv;
        outv.x = o[r][0] * inv;
        outv.y = o[r][1] * inv;
        outv.z = o[r][2] * inv;
        outv.w = o[r][3] * inv;
        *(float4*)(z + (baseRow + row) * DMODEL + h * 64 + d0) = outv;
    }
}

// ---------------- launch ----------------
extern "C" void kernel_launch(void* const* d_in, const int* in_sizes, int n_in,
                              void* d_out, int out_size)
{
    const float* x_q  = (const float*)d_in[0];
    const float* x_k  = (const float*)d_in[1];
    const float* x_v  = (const float*)d_in[2];
    const float* amsk = (const float*)d_in[3];
    const float* w_q  = (const float*)d_in[4];
    const float* w_k  = (const float*)d_in[5];
    const float* w_v  = (const float*)d_in[6];
    const float* w_o  = (const float*)d_in[7];
    const float* b_q  = (const float*)d_in[8];
    const float* b_k  = (const float*)d_in[9];
    const float* b_v  = (const float*)d_in[10];
    const float* b_o  = (const float*)d_in[11];
    float* out = (float*)d_out;

    float *gq, *gk, *gv, *gz;
    cudaGetSymbolAddress((void**)&gq, g_q);
    cudaGetSymbolAddress((void**)&gk, g_k);
    cudaGetSymbolAddress((void**)&gv, g_v);
    cudaGetSymbolAddress((void**)&gz, g_z);

    int fl_smem = 4 * 64 * FL_LDS * sizeof(float);
    cudaFuncSetAttribute(flash_attn, cudaFuncAttributeMaxDynamicSharedMemorySize, fl_smem);

    dim3 ggrid(DMODEL / 128, MROWS / 128);

    // QKV projections (tf32 mma.sync)
    tf32_gemm<<<ggrid, 256>>>(x_q, w_q, b_q, gq, 0);
    tf32_gemm<<<ggrid, 256>>>(x_k, w_k, b_k, gk, 0);
    tf32_gemm<<<ggrid, 256>>>(x_v, w_v, b_v, gv, 0);

    // flash attention
    dim3 fgrid(S_LEN / 64, NHEADS, BATCH);
    flash_attn<<<fgrid, 256, fl_smem>>>(gq, gk, gv, amsk, gz);

    // output projection
    tf32_gemm<<<ggrid, 256>>>(gz, w_o, b_o, out, 1);

    (void)in_sizes; (void)n_in; (void)out_size;
}

// round 5
// speedup vs baseline: 3.7514x; 3.7514x over previous
#include <cuda_runtime.h>
#include <cstdint>
#include <math.h>

#define S_LEN   2048
#define BATCH   2
#define DMODEL  1024
#define NHEADS  16
#define DHEAD   64
#define MROWS   (BATCH * S_LEN)   // 4096
#define IGNORE_VAL (-100000.0f)

// ---------------- scratch (no allocations allowed) ----------------
__device__ float g_q[MROWS * DMODEL];
__device__ float g_k[MROWS * DMODEL];
__device__ float g_v[MROWS * DMODEL];
__device__ float g_z[MROWS * DMODEL];

// ---------------- helpers ----------------
__device__ __forceinline__ uint32_t f2tf32(float f) {
    uint32_t r;
    asm("cvt.rna.tf32.f32 %0, %1;" : "=r"(r) : "f"(f));
    return r;
}

__device__ __forceinline__ void mma_tf32_16x8x8(
    float* d, const uint32_t* a, const uint32_t* b, const float* c)
{
    asm volatile(
        "mma.sync.aligned.m16n8k8.row.col.f32.tf32.tf32.f32 "
        "{%0,%1,%2,%3}, {%4,%5,%6,%7}, {%8,%9}, {%10,%11,%12,%13};\n"
        : "=f"(d[0]), "=f"(d[1]), "=f"(d[2]), "=f"(d[3])
        : "r"(a[0]), "r"(a[1]), "r"(a[2]), "r"(a[3]),
          "r"(b[0]), "r"(b[1]),
          "f"(c[0]), "f"(c[1]), "f"(c[2]), "f"(c[3]));
}

// ============ tf32 mma.sync GEMM (validated R3) ============
#define KC   32
#define TS   36

__global__ __launch_bounds__(256) void tf32_gemm(
    const float* __restrict__ A, const float* __restrict__ W,
    const float* __restrict__ bias, float* __restrict__ C, int mode)
{
    __shared__ uint32_t As[128 * TS];
    __shared__ uint32_t Bs[128 * TS];

    const int tid = threadIdx.x;
    const int wid = tid >> 5;
    const int lid = tid & 31;
    const int g   = lid >> 2;
    const int tig = lid & 3;
    const int wm = wid >> 2;
    const int wn = wid & 3;
    const int n0 = blockIdx.x * 128;
    const int m0 = blockIdx.y * 128;

    float acc[4][4][4];
#pragma unroll
    for (int i = 0; i < 4; i++)
#pragma unroll
        for (int j = 0; j < 4; j++)
#pragma unroll
            for (int f = 0; f < 4; f++) acc[i][j][f] = 0.0f;

    const int ng = n0 + (tid & 127);
    const int khalf = (tid >> 7) * 16;

    for (int k0 = 0; k0 < DMODEL; k0 += KC) {
        __syncthreads();
#pragma unroll
        for (int it = 0; it < 4; it++) {
            int i = tid + it * 256;
            int row = i >> 3;
            int j = i & 7;
            float4 v = *(const float4*)(A + (size_t)(m0 + row) * DMODEL + k0 + j * 4);
            uint32_t* dst = As + row * TS + j * 4;
            dst[0] = f2tf32(v.x);
            dst[1] = f2tf32(v.y);
            dst[2] = f2tf32(v.z);
            dst[3] = f2tf32(v.w);
        }
        if (mode == 0) {
            const float* wb = W + (size_t)(ng >> 6) * (DMODEL * DHEAD) + (ng & 63);
#pragma unroll
            for (int k = 0; k < 16; k++) {
                float v = wb[(size_t)(k0 + khalf + k) * DHEAD];
                Bs[(tid & 127) * TS + khalf + k] = f2tf32(v);
            }
        } else {
            const float* wb = W + ng;
#pragma unroll
            for (int k = 0; k < 16; k++) {
                float v = wb[(size_t)(k0 + khalf + k) * DMODEL];
                Bs[(tid & 127) * TS + khalf + k] = f2tf32(v);
            }
        }
        __syncthreads();

#pragma unroll
        for (int kk = 0; kk < KC; kk += 8) {
            uint32_t af[4][4];
            uint32_t bf[4][2];
#pragma unroll
            for (int mi = 0; mi < 4; mi++) {
                int r = wm * 64 + mi * 16 + g;
                af[mi][0] = As[r * TS + kk + tig];
                af[mi][1] = As[(r + 8) * TS + kk + tig];
                af[mi][2] = As[r * TS + kk + tig + 4];
                af[mi][3] = As[(r + 8) * TS + kk + tig + 4];
            }
#pragma unroll
            for (int nj = 0; nj < 4; nj++) {
                int n = wn * 32 + nj * 8 + g;
                bf[nj][0] = Bs[n * TS + kk + tig];
                bf[nj][1] = Bs[n * TS + kk + tig + 4];
            }
#pragma unroll
            for (int mi = 0; mi < 4; mi++)
#pragma unroll
                for (int nj = 0; nj < 4; nj++)
                    mma_tf32_16x8x8(acc[mi][nj], af[mi], bf[nj], acc[mi][nj]);
        }
    }

#pragma unroll
    for (int mi = 0; mi < 4; mi++) {
        int r0 = m0 + wm * 64 + mi * 16 + g;
#pragma unroll
        for (int nj = 0; nj < 4; nj++) {
            int c0 = n0 + wn * 32 + nj * 8 + tig * 2;
            float b0 = bias[c0], b1 = bias[c0 + 1];
            float2 v0 = make_float2(acc[mi][nj][0] + b0, acc[mi][nj][1] + b1);
            float2 v1 = make_float2(acc[mi][nj][2] + b0, acc[mi][nj][3] + b1);
            *(float2*)(C + (size_t)r0 * DMODEL + c0) = v0;
            *(float2*)(C + (size_t)(r0 + 8) * DMODEL + c0) = v1;
        }
    }
}

// ============ flash attention with mma.sync tf32 ============
// CTA: 128 q rows x one (h, b). 8 warps; warp w owns rows [w*16, w*16+16).
// K/V tiles of 64 rows. smem stride 68 words. P aliased over K buffer.
#define FS 68   // smem row stride in words

__global__ __launch_bounds__(256) void flash_attn_mma(
    const float* __restrict__ q, const float* __restrict__ k,
    const float* __restrict__ v, const float* __restrict__ amask,
    float* __restrict__ z)
{
    extern __shared__ uint32_t sm[];
    uint32_t* Qs  = sm;                 // 128 x FS
    uint32_t* KPs = sm + 128 * FS;      // K: rows 0..63; P: rows 0..127 (aliased)
    uint32_t* Vs  = sm + 256 * FS;      // 64 x FS  (layout [kpos][d])

    const int qt = blockIdx.x;
    const int h  = blockIdx.y;
    const int b  = blockIdx.z;
    const int tid = threadIdx.x;
    const int wid = tid >> 5;
    const int lid = tid & 31;
    const int g   = lid >> 2;
    const int tig = lid & 3;
    const int r0  = wid * 16;          // warp's row base within tile

    const size_t base = (size_t)b * S_LEN;
    const float* qp = q + (base + qt * 128) * DMODEL + h * 64;

    // load Q tile (128 x 64), convert to tf32
#pragma unroll
    for (int it = 0; it < 8; it++) {
        int i = tid + it * 256;
        int row = i >> 4;
        int j = i & 15;
        float4 val = *(const float4*)(qp + (size_t)row * DMODEL + j * 4);
        uint32_t* d = Qs + row * FS + j * 4;
        d[0] = f2tf32(val.x); d[1] = f2tf32(val.y);
        d[2] = f2tf32(val.z); d[3] = f2tf32(val.w);
    }

    float o[8][4];
#pragma unroll
    for (int nj = 0; nj < 8; nj++)
#pragma unroll
        for (int f = 0; f < 4; f++) o[nj][f] = 0.0f;
    float mrow0 = -1e30f, mrow1 = -1e30f;
    float lrow0 = 0.0f,  lrow1 = 0.0f;

    const int qi0 = qt * 128 + r0 + g;
    const int qi1 = qi0 + 8;
    const int nkt = 2 * (qt + 1);

    for (int kt = 0; kt < nkt; kt++) {
        __syncthreads();   // prior PV reads (Ps/Vs) complete before overwrite
        const float* kp = k + (base + kt * 64) * DMODEL + h * 64;
        const float* vp = v + (base + kt * 64) * DMODEL + h * 64;
#pragma unroll
        for (int it = 0; it < 4; it++) {
            int i = tid + it * 256;
            int row = i >> 4;
            int j = i & 15;
            float4 kv = *(const float4*)(kp + (size_t)row * DMODEL + j * 4);
            uint32_t* dk = KPs + row * FS + j * 4;
            dk[0] = f2tf32(kv.x); dk[1] = f2tf32(kv.y);
            dk[2] = f2tf32(kv.z); dk[3] = f2tf32(kv.w);
            float4 vv = *(const float4*)(vp + (size_t)row * DMODEL + j * 4);
            uint32_t* dv = Vs + row * FS + j * 4;
            dv[0] = f2tf32(vv.x); dv[1] = f2tf32(vv.y);
            dv[2] = f2tf32(vv.z); dv[3] = f2tf32(vv.w);
        }
        __syncthreads();

        // ---- S = Q K^T : warp tile 16 x 64 ----
        float sacc[8][4];
#pragma unroll
        for (int nj = 0; nj < 8; nj++)
#pragma unroll
            for (int f = 0; f < 4; f++) sacc[nj][f] = 0.0f;

#pragma unroll
        for (int kk = 0; kk < 64; kk += 8) {
            uint32_t a[4];
            a[0] = Qs[(r0 + g) * FS + kk + tig];
            a[1] = Qs[(r0 + g + 8) * FS + kk + tig];
            a[2] = Qs[(r0 + g) * FS + kk + tig + 4];
            a[3] = Qs[(r0 + g + 8) * FS + kk + tig + 4];
#pragma unroll
            for (int nj = 0; nj < 8; nj++) {
                uint32_t bb[2];
                bb[0] = KPs[(nj * 8 + g) * FS + kk + tig];
                bb[1] = KPs[(nj * 8 + g) * FS + kk + tig + 4];
                mma_tf32_16x8x8(sacc[nj], a, bb, sacc[nj]);
            }
        }

        // ---- scale, causal mask, additive mask ----
        float tmax0 = -1e30f, tmax1 = -1e30f;
#pragma unroll
        for (int nj = 0; nj < 8; nj++) {
            int kj = kt * 64 + nj * 8 + tig * 2;
            float am0 = amask[b * S_LEN + kj];
            float am1 = amask[b * S_LEN + kj + 1];
            float s0 = ((kj     <= qi0) ? sacc[nj][0] * 0.125f : IGNORE_VAL) + am0;
            float s1 = ((kj + 1 <= qi0) ? sacc[nj][1] * 0.125f : IGNORE_VAL) + am1;
            float s2 = ((kj     <= qi1) ? sacc[nj][2] * 0.125f : IGNORE_VAL) + am0;
            float s3 = ((kj + 1 <= qi1) ? sacc[nj][3] * 0.125f : IGNORE_VAL) + am1;
            sacc[nj][0] = s0; sacc[nj][1] = s1; sacc[nj][2] = s2; sacc[nj][3] = s3;
            tmax0 = fmaxf(tmax0, fmaxf(s0, s1));
            tmax1 = fmaxf(tmax1, fmaxf(s2, s3));
        }
        // reduce over the 4 tig lanes sharing each row
        tmax0 = fmaxf(tmax0, __shfl_xor_sync(0xffffffffu, tmax0, 1));
        tmax0 = fmaxf(tmax0, __shfl_xor_sync(0xffffffffu, tmax0, 2));
        tmax1 = fmaxf(tmax1, __shfl_xor_sync(0xffffffffu, tmax1, 1));
        tmax1 = fmaxf(tmax1, __shfl_xor_sync(0xffffffffu, tmax1, 2));

        float mn0 = fmaxf(mrow0, tmax0);
        float mn1 = fmaxf(mrow1, tmax1);
        float alpha0 = __expf(mrow0 - mn0);
        float alpha1 = __expf(mrow1 - mn1);
        mrow0 = mn0; mrow1 = mn1;

        float rs0 = 0.0f, rs1 = 0.0f;
#pragma unroll
        for (int nj = 0; nj < 8; nj++) {
            float p0 = __expf(sacc[nj][0] - mn0);
            float p1 = __expf(sacc[nj][1] - mn0);
            float p2 = __expf(sacc[nj][2] - mn1);
            float p3 = __expf(sacc[nj][3] - mn1);
            sacc[nj][0] = p0; sacc[nj][1] = p1; sacc[nj][2] = p2; sacc[nj][3] = p3;
            rs0 += p0 + p1;
            rs1 += p2 + p3;
        }
        rs0 += __shfl_xor_sync(0xffffffffu, rs0, 1);
        rs0 += __shfl_xor_sync(0xffffffffu, rs0, 2);
        rs1 += __shfl_xor_sync(0xffffffffu, rs1, 1);
        rs1 += __shfl_xor_sync(0xffffffffu, rs1, 2);
        lrow0 = lrow0 * alpha0 + rs0;
        lrow1 = lrow1 * alpha1 + rs1;

#pragma unroll
        for (int nj = 0; nj < 8; nj++) {
            o[nj][0] *= alpha0; o[nj][1] *= alpha0;
            o[nj][2] *= alpha1; o[nj][3] *= alpha1;
        }

        __syncthreads();   // all warps done reading K before P overwrites it

        // ---- stage P (tf32) into KPs, rows r0+g / r0+g+8, cols = kpos-local ----
#pragma unroll
        for (int nj = 0; nj < 8; nj++) {
            int col = nj * 8 + tig * 2;
            KPs[(r0 + g) * FS + col]     = f2tf32(sacc[nj][0]);
            KPs[(r0 + g) * FS + col + 1] = f2tf32(sacc[nj][1]);
            KPs[(r0 + g + 8) * FS + col]     = f2tf32(sacc[nj][2]);
            KPs[(r0 + g + 8) * FS + col + 1] = f2tf32(sacc[nj][3]);
        }
        __syncwarp();      // P is warp-private (same rows) — warp fence suffices

        // ---- O += P V : A = P (16 x 64 kpos), B = V (kpos x d, col-major frags) ----
#pragma unroll
        for (int kk = 0; kk < 64; kk += 8) {
            uint32_t a[4];
            a[0] = KPs[(r0 + g) * FS + kk + tig];
            a[1] = KPs[(r0 + g + 8) * FS + kk + tig];
            a[2] = KPs[(r0 + g) * FS + kk + tig + 4];
            a[3] = KPs[(r0 + g + 8) * FS + kk + tig + 4];
#pragma unroll
            for (int nj = 0; nj < 8; nj++) {
                uint32_t bb[2];
                bb[0] = Vs[(kk + tig) * FS + nj * 8 + g];
                bb[1] = Vs[(kk + tig + 4) * FS + nj * 8 + g];
                mma_tf32_16x8x8(o[nj], a, bb, o[nj]);
            }
        }
    }

    // ---- epilogue: O /= l, write z ----
    float inv0 = 1.0f / lrow0;
    float inv1 = 1.0f / lrow1;
    const size_t row0 = base + qt * 128 + r0 + g;
#pragma unroll
    for (int nj = 0; nj < 8; nj++) {
        int col = h * 64 + nj * 8 + tig * 2;
        *(float2*)(z + row0 * DMODEL + col) =
            make_float2(o[nj][0] * inv0, o[nj][1] * inv0);
        *(float2*)(z + (row0 + 8) * DMODEL + col) =
            make_float2(o[nj][2] * inv1, o[nj][3] * inv1);
    }
}

// ---------------- launch ----------------
extern "C" void kernel_launch(void* const* d_in, const int* in_sizes, int n_in,
                              void* d_out, int out_size)
{
    const float* x_q  = (const float*)d_in[0];
    const float* x_k  = (const float*)d_in[1];
    const float* x_v  = (const float*)d_in[2];
    const float* amsk = (const float*)d_in[3];
    const float* w_q  = (const float*)d_in[4];
    const float* w_k  = (const float*)d_in[5];
    const float* w_v  = (const float*)d_in[6];
    const float* w_o  = (const float*)d_in[7];
    const float* b_q  = (const float*)d_in[8];
    const float* b_k  = (const float*)d_in[9];
    const float* b_v  = (const float*)d_in[10];
    const float* b_o  = (const float*)d_in[11];
    float* out = (float*)d_out;

    float *gq, *gk, *gv, *gz;
    cudaGetSymbolAddress((void**)&gq, g_q);
    cudaGetSymbolAddress((void**)&gk, g_k);
    cudaGetSymbolAddress((void**)&gv, g_v);
    cudaGetSymbolAddress((void**)&gz, g_z);

    int fl_smem = 320 * FS * sizeof(uint32_t);   // (128+128+64) * 68 * 4 = 87,040 B
    cudaFuncSetAttribute(flash_attn_mma, cudaFuncAttributeMaxDynamicSharedMemorySize, fl_smem);

    dim3 ggrid(DMODEL / 128, MROWS / 128);

    tf32_gemm<<<ggrid, 256>>>(x_q, w_q, b_q, gq, 0);
    tf32_gemm<<<ggrid, 256>>>(x_k, w_k, b_k, gk, 0);
    tf32_gemm<<<ggrid, 256>>>(x_v, w_v, b_v, gv, 0);

    dim3 fgrid(S_LEN / 128, NHEADS, BATCH);   // (16, 16, 2)
    flash_attn_mma<<<fgrid, 256, fl_smem>>>(gq, gk, gv, amsk, gz);

    tf32_gemm<<<ggrid, 256>>>(gz, w_o, b_o, out, 1);

    (void)in_sizes; (void)n_in; (void)out_size;
}